// round 2
// baseline (speedup 1.0000x reference)
#include <cuda_runtime.h>
#include <cuda_bf16.h>
#include <cstddef>

// Problem constants
#define SS 2048
#define BB 64
#define DD 128
#define HH 128
#define GG 512   // 4*H

// 256 MB scratch for precomputed input gates: pre[t][b][512] = x@W_ih^T + b
__device__ float g_pre[(size_t)SS * BB * GG];

// ---------------------------------------------------------------------------
// Kernel P: pre = X @ W_ih^T + bias   (unchanged from R1 — ~0.4ms, not binding)
// ---------------------------------------------------------------------------
#define PSTRIDE 132
__global__ void __launch_bounds__(256) pre_gemm_kernel(
    const float* __restrict__ X,
    const float* __restrict__ Wih,
    const float* __restrict__ bias)
{
    extern __shared__ float sm[];
    float* Xs = sm;                       // [128][PSTRIDE]
    float* Ws = sm + 128 * PSTRIDE;       // [128][PSTRIDE]

    const int tid = threadIdx.x;
    const int row0 = blockIdx.x * 128;
    const int col0 = blockIdx.y * 128;

    #pragma unroll
    for (int it = 0; it < 64; it++) {
        int idx = it * 256 + tid;
        int i = idx >> 7;
        int k = idx & 127;
        Xs[k * PSTRIDE + i] = X[(size_t)(row0 + i) * DD + k];
    }
    #pragma unroll
    for (int it = 0; it < 64; it++) {
        int idx = it * 256 + tid;
        int j = idx >> 7;
        int k = idx & 127;
        Ws[k * PSTRIDE + j] = Wih[(size_t)(col0 + j) * DD + k];
    }
    __syncthreads();

    const int tx = tid & 15;
    const int ty = tid >> 4;

    float acc[8][8];
    #pragma unroll
    for (int i = 0; i < 8; i++)
        #pragma unroll
        for (int j = 0; j < 8; j++) acc[i][j] = 0.0f;

    #pragma unroll 4
    for (int k = 0; k < 128; k++) {
        float4 a0 = *(const float4*)&Xs[k * PSTRIDE + ty * 8];
        float4 a1 = *(const float4*)&Xs[k * PSTRIDE + ty * 8 + 4];
        float4 b0 = *(const float4*)&Ws[k * PSTRIDE + tx * 8];
        float4 b1 = *(const float4*)&Ws[k * PSTRIDE + tx * 8 + 4];
        float av[8] = {a0.x, a0.y, a0.z, a0.w, a1.x, a1.y, a1.z, a1.w};
        float bv[8] = {b0.x, b0.y, b0.z, b0.w, b1.x, b1.y, b1.z, b1.w};
        #pragma unroll
        for (int i = 0; i < 8; i++)
            #pragma unroll
            for (int j = 0; j < 8; j++)
                acc[i][j] += av[i] * bv[j];
    }

    const int gcol = col0 + tx * 8;
    float bv8[8];
    #pragma unroll
    for (int j = 0; j < 8; j++) bv8[j] = bias[gcol + j];

    #pragma unroll
    for (int i = 0; i < 8; i++) {
        size_t r = (size_t)(row0 + ty * 8 + i);
        float* dst = g_pre + r * GG + gcol;
        float4 v0, v1;
        v0.x = acc[i][0] + bv8[0]; v0.y = acc[i][1] + bv8[1];
        v0.z = acc[i][2] + bv8[2]; v0.w = acc[i][3] + bv8[3];
        v1.x = acc[i][4] + bv8[4]; v1.y = acc[i][5] + bv8[5];
        v1.z = acc[i][6] + bv8[6]; v1.w = acc[i][7] + bv8[7];
        *(float4*)&dst[0] = v0;
        *(float4*)&dst[4] = v1;
    }
}

// ---------------------------------------------------------------------------
// Kernel R: reverse sequential scan, 1 block/batch, 512 threads.
// Thread j owns gate row r(j) = 128*(j&3) + (j>>2)  (quadrant q = j&3).
// i,f,g,o for h-index k = j>>2 live in 4 ADJACENT LANES -> SHFL exchange,
// no barrier for the gate->state handoff. Single barrier/step with
// double-buffered h.
// W_hh[r][0:64] in registers, W_hh[r][64:128] in shared (conflict-free).
// ---------------------------------------------------------------------------
__device__ __forceinline__ float fast_tanh(float x) {
    return 1.0f - __fdividef(2.0f, __expf(2.0f * x) + 1.0f);
}

__global__ void __launch_bounds__(512, 1) lstm_rev_kernel(
    const float* __restrict__ timeArr,   // [S*B]
    const float* __restrict__ Whh,       // [512,128]
    const float* __restrict__ w_t,       // [128]
    const float* __restrict__ b_t,       // [128]
    float* __restrict__ out)             // outputs ++ h ++ c
{
    extern __shared__ float smem[];
    // layout: Wt4 (16*512 float4 = 128KB) | hbuf[2][128]
    float4* Wt4  = (float4*)smem;                 // Wt4[c4*512 + j]
    float*  hbuf = smem + 16 * 512 * 4;           // 2 x 128 floats

    const int tid   = threadIdx.x;
    const int batch = blockIdx.x;
    const int q     = tid & 3;           // gate quadrant: 0=i 1=f 2=g 3=o
    const int k     = tid >> 2;          // h-index
    const int grow  = 128 * q + k;       // gate row this thread owns

    // Register-resident first-half weights: W_hh[grow][0:64]
    float w0[64];
    #pragma unroll
    for (int c = 0; c < 64; c++)
        w0[c] = Whh[(size_t)grow * HH + c];

    // Shared second-half weights: Wt4[c4*512 + j] = W_hh[grow][64+4c4..]
    #pragma unroll
    for (int c4 = 0; c4 < 16; c4++) {
        const float* src = Whh + (size_t)grow * HH + 64 + 4 * c4;
        Wt4[c4 * 512 + tid] = make_float4(src[0], src[1], src[2], src[3]);
    }

    // decay params for this h-index (same for all 4 lanes of the group)
    const float wt = w_t[k];
    const float bt = b_t[k];
    float creg = 0.0f;         // cell state (redundant across the 4 lanes)
    float hlast = 0.0f;

    if (tid < 128) { hbuf[tid] = 0.0f; }
    __syncthreads();

    const float* preP = g_pre + (size_t)batch * GG + grow;
    float pre_next = preP[(size_t)(SS - 1) * BB * GG];
    float tv_next  = timeArr[(size_t)(SS - 1) * BB + batch];

    const unsigned lb = (tid & 31) & ~3u;    // lane base of the 4-lane group
    const float gate_mul = (q == 2) ? 2.0f : 1.0f;   // tanh = 2*sig(2x)-1

    int cur = 0;
    for (int t = SS - 1; t >= 0; t--) {
        const float pre_j = pre_next;
        const float tv    = tv_next;
        if (t > 0) {  // prefetch next step (hides DRAM latency)
            pre_next = preP[(size_t)(t - 1) * BB * GG];
            tv_next  = timeArr[(size_t)(t - 1) * BB + batch];
        }

        const float4* h4 = (const float4*)(hbuf + cur * 128);

        // gates[grow] = pre + W_hh[grow] . h
        float a0 = pre_j, a1 = 0.0f, a2 = 0.0f, a3 = 0.0f;
        #pragma unroll
        for (int c4 = 0; c4 < 16; c4++) {
            float4 hv = h4[c4];                     // broadcast
            a0 += w0[4 * c4 + 0] * hv.x;
            a1 += w0[4 * c4 + 1] * hv.y;
            a2 += w0[4 * c4 + 2] * hv.z;
            a3 += w0[4 * c4 + 3] * hv.w;
        }
        #pragma unroll
        for (int c4 = 0; c4 < 16; c4++) {
            float4 wv = Wt4[c4 * 512 + tid];        // conflict-free
            float4 hv = h4[16 + c4];                // broadcast
            a0 += wv.x * hv.x;
            a1 += wv.y * hv.y;
            a2 += wv.z * hv.z;
            a3 += wv.w * hv.w;
        }
        float g = (a0 + a1) + (a2 + a3);

        // unified activation (no divergence): s = sigmoid(m*g)
        float s = __fdividef(1.0f, 1.0f + __expf(-gate_mul * g));
        float a = (q == 2) ? (2.0f * s - 1.0f) : s;

        // exchange the 4 gate activations within the lane group
        const unsigned FULL = 0xffffffffu;
        float ai = __shfl_sync(FULL, a, lb + 0);
        float af = __shfl_sync(FULL, a, lb + 1);
        float ag = __shfl_sync(FULL, a, lb + 2);
        float ao = __shfl_sync(FULL, a, lb + 3);

        // state update (all 4 lanes compute identically)
        float dec = __expf(-fmaxf(tv * wt + bt, 0.0f));
        creg = af * creg * dec + ai * ag;
        float hv = ao * fast_tanh(creg);
        hlast = hv;

        // write h into the OTHER buffer; one barrier publishes it
        if (q == 0) {
            hbuf[(cur ^ 1) * 128 + k] = hv;
            out[(size_t)t * (BB * HH) + (size_t)batch * HH + k] = hv;
        }
        __syncthreads();
        cur ^= 1;
    }

    // final state: h then c after the outputs block
    if (q == 0) {
        size_t base = (size_t)SS * BB * HH;
        out[base + (size_t)batch * HH + k] = hlast;
        out[base + (size_t)BB * HH + (size_t)batch * HH + k] = creg;
    }
}

// ---------------------------------------------------------------------------
// Launch
// ---------------------------------------------------------------------------
extern "C" void kernel_launch(void* const* d_in, const int* in_sizes, int n_in,
                              void* d_out, int out_size)
{
    const float* X    = (const float*)d_in[0];  // input  (S,B,D)
    const float* Tm   = (const float*)d_in[1];  // time   (S,B,1)
    const float* Wih  = (const float*)d_in[2];  // (4H, D)
    const float* Whh  = (const float*)d_in[3];  // (4H, H)
    const float* bias = (const float*)d_in[4];  // (4H,)
    const float* wt   = (const float*)d_in[5];  // (H,)
    const float* bt   = (const float*)d_in[6];  // (H,)
    float* out = (float*)d_out;

    const int smemP = 2 * 128 * PSTRIDE * (int)sizeof(float);       // 135168 B
    const int smemR = (16 * 512 * 4 + 2 * 128) * (int)sizeof(float);// 132096 B
    cudaFuncSetAttribute(pre_gemm_kernel,
                         cudaFuncAttributeMaxDynamicSharedMemorySize, smemP);
    cudaFuncSetAttribute(lstm_rev_kernel,
                         cudaFuncAttributeMaxDynamicSharedMemorySize, smemR);

    dim3 gridP((SS * BB) / 128, GG / 128);
    pre_gemm_kernel<<<gridP, 256, smemP>>>(X, Wih, bias);

    lstm_rev_kernel<<<BB, 512, smemR>>>(Tm, Whh, wt, bt, out);
}

// round 3
// speedup vs baseline: 1.0090x; 1.0090x over previous
#include <cuda_runtime.h>
#include <cuda_bf16.h>
#include <cstddef>

// Problem constants
#define SS 2048
#define BB 64
#define DD 128
#define HH 128
#define GG 512   // 4*H

// 256 MB scratch for precomputed input gates: pre[t][b][512] = x@W_ih^T + b
__device__ float g_pre[(size_t)SS * BB * GG];

typedef unsigned long long ull;

// Packed fp32x2 FMA (sm_100+): d = a*b + c on both 32-bit lanes
#define FMA_F32X2(d, a, b, c) \
    asm("fma.rn.f32x2 %0, %1, %2, %3;" : "=l"(d) : "l"(a), "l"(b), "l"(c))
#define PACK_DUP(out, f) \
    asm("mov.b64 %0, {%1, %1};" : "=l"(out) : "r"(__float_as_uint(f)))
#define UNPACK2(lo, hi, in) \
    asm("mov.b64 {%0, %1}, %2;" : "=f"(lo), "=f"(hi) : "l"(in))

// ---------------------------------------------------------------------------
// Kernel P: pre = X @ W_ih^T + bias, using f32x2 packed FMA.
// ---------------------------------------------------------------------------
#define PSTRIDE 132
__global__ void __launch_bounds__(256) pre_gemm_kernel(
    const float* __restrict__ X,
    const float* __restrict__ Wih,
    const float* __restrict__ bias)
{
    extern __shared__ float sm[];
    float* Xs = sm;                       // [128][PSTRIDE]
    float* Ws = sm + 128 * PSTRIDE;       // [128][PSTRIDE]

    const int tid = threadIdx.x;
    const int row0 = blockIdx.x * 128;
    const int col0 = blockIdx.y * 128;

    #pragma unroll
    for (int it = 0; it < 64; it++) {
        int idx = it * 256 + tid;
        int i = idx >> 7;
        int k = idx & 127;
        Xs[k * PSTRIDE + i] = X[(size_t)(row0 + i) * DD + k];
    }
    #pragma unroll
    for (int it = 0; it < 64; it++) {
        int idx = it * 256 + tid;
        int j = idx >> 7;
        int k = idx & 127;
        Ws[k * PSTRIDE + j] = Wih[(size_t)(col0 + j) * DD + k];
    }
    __syncthreads();

    const int tx = tid & 15;
    const int ty = tid >> 4;

    ull acc2[8][4];   // 8 rows x 4 f32x2 pairs (= 8 cols)
    #pragma unroll
    for (int i = 0; i < 8; i++)
        #pragma unroll
        for (int j = 0; j < 4; j++) acc2[i][j] = 0ULL;

    #pragma unroll 4
    for (int k = 0; k < 128; k++) {
        float4 a0 = *(const float4*)&Xs[k * PSTRIDE + ty * 8];
        float4 a1 = *(const float4*)&Xs[k * PSTRIDE + ty * 8 + 4];
        ulonglong2 b0 = *(const ulonglong2*)&Ws[k * PSTRIDE + tx * 8];
        ulonglong2 b1 = *(const ulonglong2*)&Ws[k * PSTRIDE + tx * 8 + 4];
        float av[8] = {a0.x, a0.y, a0.z, a0.w, a1.x, a1.y, a1.z, a1.w};
        ull bp[4] = {b0.x, b0.y, b1.x, b1.y};
        #pragma unroll
        for (int i = 0; i < 8; i++) {
            ull aa;
            PACK_DUP(aa, av[i]);
            #pragma unroll
            for (int j = 0; j < 4; j++)
                FMA_F32X2(acc2[i][j], aa, bp[j], acc2[i][j]);
        }
    }

    const int gcol = col0 + tx * 8;
    float bv8[8];
    #pragma unroll
    for (int j = 0; j < 8; j++) bv8[j] = bias[gcol + j];

    #pragma unroll
    for (int i = 0; i < 8; i++) {
        size_t r = (size_t)(row0 + ty * 8 + i);
        float* dst = g_pre + r * GG + gcol;
        float res[8];
        #pragma unroll
        for (int j = 0; j < 4; j++) {
            float lo, hi;
            UNPACK2(lo, hi, acc2[i][j]);
            res[2 * j]     = lo + bv8[2 * j];
            res[2 * j + 1] = hi + bv8[2 * j + 1];
        }
        *(float4*)&dst[0] = make_float4(res[0], res[1], res[2], res[3]);
        *(float4*)&dst[4] = make_float4(res[4], res[5], res[6], res[7]);
    }
}

// ---------------------------------------------------------------------------
// Kernel R: reverse sequential scan, 1 block/batch, 512 threads.
// Split-K(2) mapping: thread t -> k = t>>2 (h-index), q = t&3 where
//   g2 = q>>1 selects gate pair (0: i,f ; 1: g,o), kh = q&1 selects K-half.
// Thread computes PARTIAL dots (K-half kh) for BOTH rows of its gate pair:
//   rowA = 128*(2*g2) + k, rowB = 128*(2*g2+1) + k.
// After a shfl_xor(1) reduce, thread owns the FULL dot of gate row q for
// h-index k -> activation -> 4-lane shfl exchange -> state update (q==0).
// rowA weights (64 floats) live in registers as f32x2 pairs; rowB weights
// stream from shared (conflict-free LDS.128). All FMAs are packed f32x2.
// ---------------------------------------------------------------------------
__device__ __forceinline__ float fast_tanh(float x) {
    return 1.0f - __fdividef(2.0f, __expf(2.0f * x) + 1.0f);
}

__global__ void __launch_bounds__(512, 1) lstm_rev_kernel(
    const float* __restrict__ timeArr,   // [S*B]
    const float* __restrict__ Whh,       // [512,128]
    const float* __restrict__ w_t,       // [128]
    const float* __restrict__ b_t,       // [128]
    float* __restrict__ out)             // outputs ++ h ++ c
{
    extern __shared__ float smem[];
    // layout: WsB (16*512 float4 = 128KB) | hbuf[2][128]
    float*  WsB  = smem;                        // rowB weights, [c4*512 + tid]
    float*  hbuf = smem + 16 * 512 * 4;         // 2 x 128 floats

    const int tid   = threadIdx.x;
    const int batch = blockIdx.x;
    const int q     = tid & 3;           // owned gate: 0=i 1=f 2=g 3=o
    const int k     = tid >> 2;          // h-index
    const int g2    = q >> 1;            // gate pair
    const int kh    = q & 1;             // K-half
    const int rowA  = 128 * (2 * g2) + k;
    const int rowB  = 128 * (2 * g2 + 1) + k;
    const int growO = 128 * q + k;       // own gate row (for pre)

    // rowA K-half weights in registers (32 f32x2 pairs = 64 floats)
    ull wA[32];
    {
        const float* src = Whh + (size_t)rowA * HH + 64 * kh;
        #pragma unroll
        for (int c = 0; c < 32; c++)
            wA[c] = *(const ull*)&src[2 * c];
    }
    // rowB K-half weights into shared: WsB[c4*512 + tid] = float4
    {
        const float* src = Whh + (size_t)rowB * HH + 64 * kh;
        #pragma unroll
        for (int c4 = 0; c4 < 16; c4++)
            *(float4*)&WsB[(c4 * 512 + tid) * 4] =
                make_float4(src[4*c4], src[4*c4+1], src[4*c4+2], src[4*c4+3]);
    }

    const float wt = w_t[k];
    const float bt = b_t[k];
    float creg = 0.0f, hlast = 0.0f;

    if (tid < 128) { hbuf[tid] = 0.0f; }
    __syncthreads();

    const float* preP = g_pre + (size_t)batch * GG + growO;
    float pre_next = preP[(size_t)(SS - 1) * BB * GG];
    float tv_next  = timeArr[(size_t)(SS - 1) * BB + batch];

    const unsigned lb = (tid & 31) & ~3u;            // lane base of group
    const float gate_mul = (q == 2) ? 2.0f : 1.0f;   // tanh = 2*sig(2x)-1
    const unsigned FULL = 0xffffffffu;

    int cur = 0;
    for (int t = SS - 1; t >= 0; t--) {
        const float pre_j = pre_next;
        const float tv    = tv_next;
        if (t > 0) {
            pre_next = preP[(size_t)(t - 1) * BB * GG];
            tv_next  = timeArr[(size_t)(t - 1) * BB + batch];
        }

        // h K-half for this thread (16 x LDS.128, 2 addrs per warp-instr)
        const ulonglong2* hU =
            (const ulonglong2*)(hbuf + cur * 128 + 64 * kh);
        const ulonglong2* wU = (const ulonglong2*)WsB;

        ull aA0 = 0ULL, aA1 = 0ULL, aB0 = 0ULL, aB1 = 0ULL;
        #pragma unroll
        for (int c4 = 0; c4 < 16; c4++) {
            ulonglong2 hv = hU[c4];                 // h[64kh+4c4 ..]
            ulonglong2 wv = wU[c4 * 512 + tid];     // rowB weights
            FMA_F32X2(aA0, wA[2 * c4],     hv.x, aA0);
            FMA_F32X2(aA1, wA[2 * c4 + 1], hv.y, aA1);
            FMA_F32X2(aB0, wv.x,           hv.x, aB0);
            FMA_F32X2(aB1, wv.y,           hv.y, aB1);
        }
        float x0, x1, y0, y1;
        UNPACK2(x0, x1, aA0); UNPACK2(y0, y1, aA1);
        float pA = (x0 + x1) + (y0 + y1);
        UNPACK2(x0, x1, aB0); UNPACK2(y0, y1, aB1);
        float pB = (x0 + x1) + (y0 + y1);

        // combine K-halves across the kh pair (lane ^ 1)
        pA += __shfl_xor_sync(FULL, pA, 1);
        pB += __shfl_xor_sync(FULL, pB, 1);

        // own full gate pre-activation
        float g = pre_j + (kh ? pB : pA);

        // unified activation: s = sigmoid(mul*g); tanh via 2s-1
        float s = __fdividef(1.0f, 1.0f + __expf(-gate_mul * g));
        float a = (q == 2) ? (2.0f * s - 1.0f) : s;

        // exchange the 4 gate activations within the lane group
        float ai = __shfl_sync(FULL, a, lb + 0);
        float af = __shfl_sync(FULL, a, lb + 1);
        float ag = __shfl_sync(FULL, a, lb + 2);
        float ao = __shfl_sync(FULL, a, lb + 3);

        // state update in q==0 lanes only
        if (q == 0) {
            float dec = __expf(-fmaxf(tv * wt + bt, 0.0f));
            creg = af * creg * dec + ai * ag;
            float hv = ao * fast_tanh(creg);
            hlast = hv;
            hbuf[(cur ^ 1) * 128 + k] = hv;
            out[(size_t)t * (BB * HH) + (size_t)batch * HH + k] = hv;
        }
        __syncthreads();
        cur ^= 1;
    }

    if (q == 0) {
        size_t base = (size_t)SS * BB * HH;
        out[base + (size_t)batch * HH + k] = hlast;
        out[base + (size_t)BB * HH + (size_t)batch * HH + k] = creg;
    }
}

// ---------------------------------------------------------------------------
// Launch
// ---------------------------------------------------------------------------
extern "C" void kernel_launch(void* const* d_in, const int* in_sizes, int n_in,
                              void* d_out, int out_size)
{
    const float* X    = (const float*)d_in[0];  // input  (S,B,D)
    const float* Tm   = (const float*)d_in[1];  // time   (S,B,1)
    const float* Wih  = (const float*)d_in[2];  // (4H, D)
    const float* Whh  = (const float*)d_in[3];  // (4H, H)
    const float* bias = (const float*)d_in[4];  // (4H,)
    const float* wt   = (const float*)d_in[5];  // (H,)
    const float* bt   = (const float*)d_in[6];  // (H,)
    float* out = (float*)d_out;

    const int smemP = 2 * 128 * PSTRIDE * (int)sizeof(float);       // 135168 B
    const int smemR = (16 * 512 * 4 + 2 * 128) * (int)sizeof(float);// 132096 B
    cudaFuncSetAttribute(pre_gemm_kernel,
                         cudaFuncAttributeMaxDynamicSharedMemorySize, smemP);
    cudaFuncSetAttribute(lstm_rev_kernel,
                         cudaFuncAttributeMaxDynamicSharedMemorySize, smemR);

    dim3 gridP((SS * BB) / 128, GG / 128);
    pre_gemm_kernel<<<gridP, 256, smemP>>>(X, Wih, bias);

    lstm_rev_kernel<<<BB, 512, smemR>>>(Tm, Whh, wt, bt, out);
}

// round 5
// speedup vs baseline: 1.0337x; 1.0244x over previous
#include <cuda_runtime.h>
#include <cuda_bf16.h>
#include <cstddef>
#include <cstdint>

// Problem constants
#define SS 2048
#define BB 64
#define DD 128
#define HH 128
#define GG 512   // 4*H

// 256 MB scratch for precomputed input gates: pre[t][b][512] = x@W_ih^T + b
__device__ float g_pre[(size_t)SS * BB * GG];

typedef unsigned long long ull;

// Packed fp32x2 FMA (sm_100+)
#define FMA_F32X2(d, a, b, c) \
    asm("fma.rn.f32x2 %0, %1, %2, %3;" : "=l"(d) : "l"(a), "l"(b), "l"(c))
#define PACK_DUP(out, f) \
    asm("mov.b64 %0, {%1, %1};" : "=l"(out) : "r"(__float_as_uint(f)))
#define UNPACK2(lo, hi, in) \
    asm("mov.b64 {%0, %1}, %2;" : "=f"(lo), "=f"(hi) : "l"(in))

// ---------------------------------------------------------------------------
// Kernel P: pre = X @ W_ih^T + bias (f32x2 version, passing since R3)
// ---------------------------------------------------------------------------
#define PSTRIDE 132
__global__ void __launch_bounds__(256) pre_gemm_kernel(
    const float* __restrict__ X,
    const float* __restrict__ Wih,
    const float* __restrict__ bias)
{
    extern __shared__ float sm[];
    float* Xs = sm;                       // [128][PSTRIDE]
    float* Ws = sm + 128 * PSTRIDE;       // [128][PSTRIDE]

    const int tid = threadIdx.x;
    const int row0 = blockIdx.x * 128;
    const int col0 = blockIdx.y * 128;

    #pragma unroll
    for (int it = 0; it < 64; it++) {
        int idx = it * 256 + tid;
        int i = idx >> 7;
        int k = idx & 127;
        Xs[k * PSTRIDE + i] = X[(size_t)(row0 + i) * DD + k];
    }
    #pragma unroll
    for (int it = 0; it < 64; it++) {
        int idx = it * 256 + tid;
        int j = idx >> 7;
        int k = idx & 127;
        Ws[k * PSTRIDE + j] = Wih[(size_t)(col0 + j) * DD + k];
    }
    __syncthreads();

    const int tx = tid & 15;
    const int ty = tid >> 4;

    ull acc2[8][4];
    #pragma unroll
    for (int i = 0; i < 8; i++)
        #pragma unroll
        for (int j = 0; j < 4; j++) acc2[i][j] = 0ULL;

    #pragma unroll 4
    for (int k = 0; k < 128; k++) {
        float4 a0 = *(const float4*)&Xs[k * PSTRIDE + ty * 8];
        float4 a1 = *(const float4*)&Xs[k * PSTRIDE + ty * 8 + 4];
        ulonglong2 b0 = *(const ulonglong2*)&Ws[k * PSTRIDE + tx * 8];
        ulonglong2 b1 = *(const ulonglong2*)&Ws[k * PSTRIDE + tx * 8 + 4];
        float av[8] = {a0.x, a0.y, a0.z, a0.w, a1.x, a1.y, a1.z, a1.w};
        ull bp[4] = {b0.x, b0.y, b1.x, b1.y};
        #pragma unroll
        for (int i = 0; i < 8; i++) {
            ull aa;
            PACK_DUP(aa, av[i]);
            #pragma unroll
            for (int j = 0; j < 4; j++)
                FMA_F32X2(acc2[i][j], aa, bp[j], acc2[i][j]);
        }
    }

    const int gcol = col0 + tx * 8;
    float bv8[8];
    #pragma unroll
    for (int j = 0; j < 8; j++) bv8[j] = bias[gcol + j];

    #pragma unroll
    for (int i = 0; i < 8; i++) {
        size_t r = (size_t)(row0 + ty * 8 + i);
        float* dst = g_pre + r * GG + gcol;
        float res[8];
        #pragma unroll
        for (int j = 0; j < 4; j++) {
            float lo, hi;
            UNPACK2(lo, hi, acc2[i][j]);
            res[2 * j]     = lo + bv8[2 * j];
            res[2 * j + 1] = hi + bv8[2 * j + 1];
        }
        *(float4*)&dst[0] = make_float4(res[0], res[1], res[2], res[3]);
        *(float4*)&dst[4] = make_float4(res[4], res[5], res[6], res[7]);
    }
}

// ---------------------------------------------------------------------------
// Cluster helpers
// ---------------------------------------------------------------------------
__device__ __forceinline__ uint32_t smem_u32(const void* p) {
    uint32_t a;
    asm("{ .reg .u64 t; cvta.to.shared.u64 t, %1; cvt.u32.u64 %0, t; }"
        : "=r"(a) : "l"(p));
    return a;
}
__device__ __forceinline__ uint32_t my_ctarank() {
    uint32_t r;
    asm("mov.u32 %0, %%cluster_ctarank;" : "=r"(r));
    return r;
}
__device__ __forceinline__ uint32_t mapa_u32(uint32_t local, uint32_t rank) {
    uint32_t r;
    asm("mapa.shared::cluster.u32 %0, %1, %2;" : "=r"(r) : "r"(local), "r"(rank));
    return r;
}
__device__ __forceinline__ void st_remote_f32(uint32_t addr, float v) {
    asm volatile("st.shared::cluster.f32 [%0], %1;" :: "r"(addr), "f"(v) : "memory");
}
// FIX (R5): explicit cluster-scope RELEASE on the remote arrive. The bare
// form defaults to .release.CTA, which does NOT order the preceding
// st.shared::cluster data store for the peer's cluster-scope acquire ->
// peer could observe the count without the data (root cause of R4's 1e-1
// rel_err). fence.acq_rel.cluster is belt-and-suspenders.
__device__ __forceinline__ void arrive_remote(uint32_t addr) {
    asm volatile(
        "fence.acq_rel.cluster;\n\t"
        "mbarrier.arrive.release.cluster.shared::cluster.b64 _, [%0];"
        :: "r"(addr) : "memory");
}
__device__ __forceinline__ void mbar_init(uint32_t addr, uint32_t count) {
    asm volatile("mbarrier.init.shared.b64 [%0], %1;"
                 :: "r"(addr), "r"(count) : "memory");
}
__device__ __forceinline__ void mbar_wait_cluster(uint32_t mbar, uint32_t parity) {
    asm volatile(
        "{\n\t"
        ".reg .pred P;\n"
        "WL_%=:\n\t"
        "mbarrier.try_wait.parity.acquire.cluster.shared::cta.b64 P, [%0], %1, 0x989680;\n\t"
        "@P bra WD_%=;\n\t"
        "bra WL_%=;\n"
        "WD_%=:\n\t"
        "}"
        :: "r"(mbar), "r"(parity) : "memory");
}
__device__ __forceinline__ void cluster_sync_hw() {
    asm volatile("barrier.cluster.arrive.aligned;" ::: "memory");
    asm volatile("barrier.cluster.wait.aligned;" ::: "memory");
}

__device__ __forceinline__ float fast_tanh(float x) {
    return 1.0f - __fdividef(2.0f, __expf(2.0f * x) + 1.0f);
}

// ---------------------------------------------------------------------------
// Kernel R: reverse scan, one 2-CTA CLUSTER per batch element.
// rank0 owns gate rows 0:256 (i, f); rank1 owns 256:512 (g, o).
// 256 threads/CTA, thread j owns global gate row = rank*256 + j, with ALL
// 128 W_hh weights register-resident (zero smem weight streaming).
// Per step: dots -> activations -> DSMEM exchange of 256 acts (per-thread
// st.shared::cluster + RELEASE.CLUSTER mbarrier arrive, count=256, 2
// mbarriers ping-pong) -> both CTAs redundantly compute c/h (bit-identical).
// ---------------------------------------------------------------------------
__global__ void __launch_bounds__(256, 1) __cluster_dims__(2, 1, 1)
lstm_rev_cluster_kernel(
    const float* __restrict__ timeArr,   // [S*B]
    const float* __restrict__ Whh,       // [512,128]
    const float* __restrict__ w_t,       // [128]
    const float* __restrict__ b_t,       // [128]
    float* __restrict__ out)             // outputs ++ h ++ c
{
    __shared__ float hbuf[2][128];
    __shared__ float act_loc[256];
    __shared__ float act_recv[2][256];
    __shared__ ull   mbars[2];

    const int tid   = threadIdx.x;
    const uint32_t rank  = my_ctarank();
    const uint32_t prank = 1u - rank;
    const int batch = blockIdx.x >> 1;
    const int grow  = (int)rank * 256 + tid;   // global gate row

    // ALL weights register-resident: 64 ull = 128 floats
    ull wR[64];
    {
        const ull* wp = (const ull*)(Whh + (size_t)grow * HH);
        #pragma unroll
        for (int c = 0; c < 64; c++) wR[c] = wp[c];
    }

    // Remote addresses (peer's act_recv slots + peer's mbarriers)
    const uint32_t mbar0_l = smem_u32(&mbars[0]);
    const uint32_t mbar1_l = smem_u32(&mbars[1]);
    const uint32_t rem_act0 = mapa_u32(smem_u32(&act_recv[0][tid]), prank);
    const uint32_t rem_act1 = mapa_u32(smem_u32(&act_recv[1][tid]), prank);
    const uint32_t rem_mb0  = mapa_u32(mbar0_l, prank);
    const uint32_t rem_mb1  = mapa_u32(mbar1_l, prank);

    if (tid == 0) {
        mbar_init(mbar0_l, 256);
        mbar_init(mbar1_l, 256);
    }
    if (tid < 128) hbuf[0][tid] = 0.0f;

    const float wt = w_t[tid & 127];
    const float bt = b_t[tid & 127];
    float creg = 0.0f, hlast = 0.0f;

    __syncthreads();
    cluster_sync_hw();   // mbarriers visible cluster-wide before any arrive

    const float* preP = g_pre + (size_t)batch * GG + grow;
    float pre_next = preP[(size_t)(SS - 1) * BB * GG];
    float tv_next  = timeArr[(size_t)(SS - 1) * BB + batch];

    const bool  is_g     = (rank == 1) && (tid < 128);
    const float gate_mul = is_g ? 2.0f : 1.0f;    // tanh = 2*sigmoid(2x)-1

    for (int s = 0; s < SS; s++) {
        const int t   = SS - 1 - s;
        const int cur = s & 1;
        const int m   = s & 1;
        const uint32_t par = (uint32_t)((s >> 1) & 1);

        const float pre_j = pre_next;
        const float tv    = tv_next;
        if (t > 0) {
            pre_next = preP[(size_t)(t - 1) * BB * GG];
            tv_next  = timeArr[(size_t)(t - 1) * BB + batch];
        }

        // dot: gates[grow] = pre + W_hh[grow] . h   (weights in regs)
        const ulonglong2* h2 = (const ulonglong2*)&hbuf[cur][0];
        ull a0 = 0ULL, a1 = 0ULL, a2 = 0ULL, a3 = 0ULL;
        #pragma unroll
        for (int i = 0; i < 32; i += 2) {
            ulonglong2 hva = h2[i];
            ulonglong2 hvb = h2[i + 1];
            FMA_F32X2(a0, wR[2 * i],     hva.x, a0);
            FMA_F32X2(a1, wR[2 * i + 1], hva.y, a1);
            FMA_F32X2(a2, wR[2 * i + 2], hvb.x, a2);
            FMA_F32X2(a3, wR[2 * i + 3], hvb.y, a3);
        }
        float x0, x1, y0, y1, z0, z1, u0, u1;
        UNPACK2(x0, x1, a0); UNPACK2(y0, y1, a1);
        UNPACK2(z0, z1, a2); UNPACK2(u0, u1, a3);
        float g = pre_j + ((x0 + x1) + (y0 + y1)) + ((z0 + z1) + (u0 + u1));

        // activation: s = sigmoid(mul*g); tanh(g) = 2*sigmoid(2g)-1
        float sg = __fdividef(1.0f, 1.0f + __expf(-gate_mul * g));
        float a  = is_g ? (2.0f * sg - 1.0f) : sg;

        // publish act: local smem + remote DSMEM + release.cluster arrive
        act_loc[tid] = a;
        st_remote_f32(m ? rem_act1 : rem_act0, a);
        arrive_remote(m ? rem_mb1 : rem_mb0);

        __syncthreads();                                  // local acts visible
        mbar_wait_cluster(m ? mbar1_l : mbar0_l, par);    // peer acts visible

        if (tid < 128) {
            const float* pIF = rank ? &act_recv[m][0] : act_loc;
            const float* pGO = rank ? act_loc : &act_recv[m][0];
            float iv = pIF[tid];
            float fv = pIF[128 + tid];
            float gv = pGO[tid];
            float ov = pGO[128 + tid];
            float dec = __expf(-fmaxf(tv * wt + bt, 0.0f));
            creg = fv * creg * dec + iv * gv;
            float hv = ov * fast_tanh(creg);
            hlast = hv;
            hbuf[cur ^ 1][tid] = hv;
            if (rank == 0)
                out[(size_t)t * (BB * HH) + (size_t)batch * HH + tid] = hv;
        }
        __syncthreads();                       // h published for next step
    }

    // final state: h then c after the outputs block (rank0 only)
    if (rank == 0 && tid < 128) {
        size_t base = (size_t)SS * BB * HH;
        out[base + (size_t)batch * HH + tid] = hlast;
        out[base + (size_t)BB * HH + (size_t)batch * HH + tid] = creg;
    }

    cluster_sync_hw();   // no early exit while peer ops in flight
}

// ---------------------------------------------------------------------------
// Launch
// ---------------------------------------------------------------------------
extern "C" void kernel_launch(void* const* d_in, const int* in_sizes, int n_in,
                              void* d_out, int out_size)
{
    const float* X    = (const float*)d_in[0];  // input  (S,B,D)
    const float* Tm   = (const float*)d_in[1];  // time   (S,B,1)
    const float* Wih  = (const float*)d_in[2];  // (4H, D)
    const float* Whh  = (const float*)d_in[3];  // (4H, H)
    const float* bias = (const float*)d_in[4];  // (4H,)
    const float* wt   = (const float*)d_in[5];  // (H,)
    const float* bt   = (const float*)d_in[6];  // (H,)
    float* out = (float*)d_out;

    const int smemP = 2 * 128 * PSTRIDE * (int)sizeof(float);  // 135168 B
    cudaFuncSetAttribute(pre_gemm_kernel,
                         cudaFuncAttributeMaxDynamicSharedMemorySize, smemP);

    dim3 gridP((SS * BB) / 128, GG / 128);
    pre_gemm_kernel<<<gridP, 256, smemP>>>(X, Wih, bias);

    // 64 clusters of 2 CTAs (grid 128), 256 threads each
    lstm_rev_cluster_kernel<<<BB * 2, 256>>>(Tm, Whh, wt, bt, out);
}

// round 6
// speedup vs baseline: 1.7601x; 1.7027x over previous
#include <cuda_runtime.h>
#include <cuda_bf16.h>
#include <cstddef>
#include <cstdint>

// Problem constants
#define SS 2048
#define BB 64
#define DD 128
#define HH 128
#define GG 512   // 4*H

// 256 MB scratch for precomputed input gates: pre[t][b][512] = x@W_ih^T + b
__device__ float g_pre[(size_t)SS * BB * GG];

typedef unsigned long long ull;

// Packed fp32x2 FMA (sm_100+)
#define FMA_F32X2(d, a, b, c) \
    asm("fma.rn.f32x2 %0, %1, %2, %3;" : "=l"(d) : "l"(a), "l"(b), "l"(c))
#define PACK_DUP(out, f) \
    asm("mov.b64 %0, {%1, %1};" : "=l"(out) : "r"(__float_as_uint(f)))
#define UNPACK2(lo, hi, in) \
    asm("mov.b64 {%0, %1}, %2;" : "=f"(lo), "=f"(hi) : "l"(in))

// ---------------------------------------------------------------------------
// Kernel P: pre = X @ W_ih^T + bias (f32x2 version, passing since R3)
// ---------------------------------------------------------------------------
#define PSTRIDE 132
__global__ void __launch_bounds__(256) pre_gemm_kernel(
    const float* __restrict__ X,
    const float* __restrict__ Wih,
    const float* __restrict__ bias)
{
    extern __shared__ float sm[];
    float* Xs = sm;                       // [128][PSTRIDE]
    float* Ws = sm + 128 * PSTRIDE;       // [128][PSTRIDE]

    const int tid = threadIdx.x;
    const int row0 = blockIdx.x * 128;
    const int col0 = blockIdx.y * 128;

    #pragma unroll
    for (int it = 0; it < 64; it++) {
        int idx = it * 256 + tid;
        int i = idx >> 7;
        int k = idx & 127;
        Xs[k * PSTRIDE + i] = X[(size_t)(row0 + i) * DD + k];
    }
    #pragma unroll
    for (int it = 0; it < 64; it++) {
        int idx = it * 256 + tid;
        int j = idx >> 7;
        int k = idx & 127;
        Ws[k * PSTRIDE + j] = Wih[(size_t)(col0 + j) * DD + k];
    }
    __syncthreads();

    const int tx = tid & 15;
    const int ty = tid >> 4;

    ull acc2[8][4];
    #pragma unroll
    for (int i = 0; i < 8; i++)
        #pragma unroll
        for (int j = 0; j < 4; j++) acc2[i][j] = 0ULL;

    #pragma unroll 4
    for (int k = 0; k < 128; k++) {
        float4 a0 = *(const float4*)&Xs[k * PSTRIDE + ty * 8];
        float4 a1 = *(const float4*)&Xs[k * PSTRIDE + ty * 8 + 4];
        ulonglong2 b0 = *(const ulonglong2*)&Ws[k * PSTRIDE + tx * 8];
        ulonglong2 b1 = *(const ulonglong2*)&Ws[k * PSTRIDE + tx * 8 + 4];
        float av[8] = {a0.x, a0.y, a0.z, a0.w, a1.x, a1.y, a1.z, a1.w};
        ull bp[4] = {b0.x, b0.y, b1.x, b1.y};
        #pragma unroll
        for (int i = 0; i < 8; i++) {
            ull aa;
            PACK_DUP(aa, av[i]);
            #pragma unroll
            for (int j = 0; j < 4; j++)
                FMA_F32X2(acc2[i][j], aa, bp[j], acc2[i][j]);
        }
    }

    const int gcol = col0 + tx * 8;
    float bv8[8];
    #pragma unroll
    for (int j = 0; j < 8; j++) bv8[j] = bias[gcol + j];

    #pragma unroll
    for (int i = 0; i < 8; i++) {
        size_t r = (size_t)(row0 + ty * 8 + i);
        float* dst = g_pre + r * GG + gcol;
        float res[8];
        #pragma unroll
        for (int j = 0; j < 4; j++) {
            float lo, hi;
            UNPACK2(lo, hi, acc2[i][j]);
            res[2 * j]     = lo + bv8[2 * j];
            res[2 * j + 1] = hi + bv8[2 * j + 1];
        }
        *(float4*)&dst[0] = make_float4(res[0], res[1], res[2], res[3]);
        *(float4*)&dst[4] = make_float4(res[4], res[5], res[6], res[7]);
    }
}

// ---------------------------------------------------------------------------
// Cluster helpers
// ---------------------------------------------------------------------------
__device__ __forceinline__ uint32_t smem_u32(const void* p) {
    uint32_t a;
    asm("{ .reg .u64 t; cvta.to.shared.u64 t, %1; cvt.u32.u64 %0, t; }"
        : "=r"(a) : "l"(p));
    return a;
}
__device__ __forceinline__ uint32_t my_ctarank() {
    uint32_t r;
    asm("mov.u32 %0, %%cluster_ctarank;" : "=r"(r));
    return r;
}
__device__ __forceinline__ uint32_t mapa_u32(uint32_t local, uint32_t rank) {
    uint32_t r;
    asm("mapa.shared::cluster.u32 %0, %1, %2;" : "=r"(r) : "r"(local), "r"(rank));
    return r;
}
__device__ __forceinline__ void mbar_init(uint32_t addr, uint32_t count) {
    asm volatile("mbarrier.init.shared.b64 [%0], %1;"
                 :: "r"(addr), "r"(count) : "memory");
}
// Async store with HW transaction tracking: data + barrier signal in one
// instruction, no fence, no per-thread arrive. dst & mbar are cluster-space
// addresses into the SAME destination CTA.
__device__ __forceinline__ void st_async_f32(uint32_t dst, float v, uint32_t mbar) {
    asm volatile(
        "st.async.shared::cluster.mbarrier::complete_tx::bytes.b32 [%0], %1, [%2];"
        :: "r"(dst), "r"(__float_as_uint(v)), "r"(mbar) : "memory");
}
__device__ __forceinline__ void mbar_expect_tx(uint32_t mbar, uint32_t bytes) {
    asm volatile("mbarrier.arrive.expect_tx.shared.b64 _, [%0], %1;"
                 :: "r"(mbar), "r"(bytes) : "memory");
}
__device__ __forceinline__ void mbar_wait(uint32_t mbar, uint32_t parity) {
    asm volatile(
        "{\n\t"
        ".reg .pred P;\n"
        "WL_%=:\n\t"
        "mbarrier.try_wait.parity.acquire.cta.shared::cta.b64 P, [%0], %1, 0x989680;\n\t"
        "@P bra WD_%=;\n\t"
        "bra WL_%=;\n"
        "WD_%=:\n\t"
        "}"
        :: "r"(mbar), "r"(parity) : "memory");
}
__device__ __forceinline__ void cluster_sync_hw() {
    asm volatile("barrier.cluster.arrive.aligned;" ::: "memory");
    asm volatile("barrier.cluster.wait.aligned;" ::: "memory");
}

__device__ __forceinline__ float fast_tanh(float x) {
    return 1.0f - __fdividef(2.0f, __expf(2.0f * x) + 1.0f);
}

// ---------------------------------------------------------------------------
// Kernel R: reverse scan, one 2-CTA CLUSTER per batch element.
// rank0 owns gate rows 0:256 (i,f); rank1 owns 256:512 (g,o). 256 thr/CTA,
// ALL 128 W_hh weights per thread register-resident.
// Exchange: each thread st.async's its activation into act_all[m][grow] of
// BOTH CTAs; each CTA's ping-pong mbarrier expects 512*4B tx + 1 arrive
// (tid0 re-arms 2 steps ahead). One wait replaces fence+256 arrives+bar.
// Both CTAs redundantly (bit-identically) compute the c/h update.
// ---------------------------------------------------------------------------
__global__ void __launch_bounds__(256, 1) __cluster_dims__(2, 1, 1)
lstm_rev_cluster_kernel(
    const float* __restrict__ timeArr,   // [S*B]
    const float* __restrict__ Whh,       // [512,128]
    const float* __restrict__ w_t,       // [128]
    const float* __restrict__ b_t,       // [128]
    float* __restrict__ out)             // outputs ++ h ++ c
{
    __shared__ __align__(16) float hbuf[2][128];
    __shared__ float act_all[2][512];
    __shared__ ull   mbars[2];

    const int tid   = threadIdx.x;
    const uint32_t rank  = my_ctarank();
    const uint32_t prank = 1u - rank;
    const int batch = blockIdx.x >> 1;
    const int grow  = (int)rank * 256 + tid;   // global gate row

    // ALL weights register-resident: 64 ull = 128 floats
    ull wR[64];
    {
        const ull* wp = (const ull*)(Whh + (size_t)grow * HH);
        #pragma unroll
        for (int c = 0; c < 64; c++) wR[c] = wp[c];
    }

    // Cluster-space addresses: my act slot in BOTH CTAs + both CTAs' mbars
    const uint32_t mb0_l = smem_u32(&mbars[0]);
    const uint32_t mb1_l = smem_u32(&mbars[1]);
    uint32_t dst_own[2], dst_peer[2], mb_own[2], mb_peer[2];
    #pragma unroll
    for (int m = 0; m < 2; m++) {
        uint32_t a = smem_u32(&act_all[m][grow]);
        dst_own[m]  = mapa_u32(a, rank);
        dst_peer[m] = mapa_u32(a, prank);
        uint32_t mb = (m == 0) ? mb0_l : mb1_l;
        mb_own[m]   = mapa_u32(mb, rank);
        mb_peer[m]  = mapa_u32(mb, prank);
    }

    if (tid == 0) {
        mbar_init(mb0_l, 1);
        mbar_init(mb1_l, 1);
        // pre-arm both barriers for steps 0 and 1 (512 floats = 2048 B each)
        mbar_expect_tx(mb0_l, 2048);
        mbar_expect_tx(mb1_l, 2048);
    }
    if (tid < 128) hbuf[0][tid] = 0.0f;

    const float wt = w_t[tid & 127];
    const float bt = b_t[tid & 127];
    float creg = 0.0f, hlast = 0.0f;

    __syncthreads();
    cluster_sync_hw();   // mbars init+armed visible cluster-wide

    const float* preP = g_pre + (size_t)batch * GG + grow;
    float pre_next = preP[(size_t)(SS - 1) * BB * GG];
    float tv_next  = timeArr[(size_t)(SS - 1) * BB + batch];

    const bool  is_g     = (rank == 1) && (tid < 128);
    const float gate_mul = is_g ? 2.0f : 1.0f;    // tanh = 2*sigmoid(2x)-1

    for (int s = 0; s < SS; s++) {
        const int t   = SS - 1 - s;
        const int cur = s & 1;
        const int m   = s & 1;
        const uint32_t par = (uint32_t)((s >> 1) & 1);

        const float pre_j = pre_next;
        const float tv    = tv_next;
        if (t > 0) {
            pre_next = preP[(size_t)(t - 1) * BB * GG];
            tv_next  = timeArr[(size_t)(t - 1) * BB + batch];
        }

        // dot: gates[grow] = pre + W_hh[grow].h  (weights in regs,
        // 8 independent accumulator chains -> dep depth 8)
        const ulonglong2* h2 = (const ulonglong2*)&hbuf[cur][0];
        ull ac[8];
        #pragma unroll
        for (int i = 0; i < 8; i++) ac[i] = 0ULL;
        #pragma unroll
        for (int i = 0; i < 8; i++) {
            ulonglong2 hva = h2[4 * i];
            ulonglong2 hvb = h2[4 * i + 1];
            ulonglong2 hvc = h2[4 * i + 2];
            ulonglong2 hvd = h2[4 * i + 3];
            FMA_F32X2(ac[0], wR[8 * i],     hva.x, ac[0]);
            FMA_F32X2(ac[1], wR[8 * i + 1], hva.y, ac[1]);
            FMA_F32X2(ac[2], wR[8 * i + 2], hvb.x, ac[2]);
            FMA_F32X2(ac[3], wR[8 * i + 3], hvb.y, ac[3]);
            FMA_F32X2(ac[4], wR[8 * i + 4], hvc.x, ac[4]);
            FMA_F32X2(ac[5], wR[8 * i + 5], hvc.y, ac[5]);
            FMA_F32X2(ac[6], wR[8 * i + 6], hvd.x, ac[6]);
            FMA_F32X2(ac[7], wR[8 * i + 7], hvd.y, ac[7]);
        }
        FMA_F32X2(ac[0], 0ULL, 0ULL, ac[0]);  // no-op keep
        ull r0, r1, r2, r3;
        // pairwise packed adds via fma(1,x,y)? simpler: unpack tree
        float f0, f1, f2, f3, f4, f5, f6, f7, g0, g1, g2, g3, g4, g5, g6, g7;
        UNPACK2(f0, f1, ac[0]); UNPACK2(f2, f3, ac[1]);
        UNPACK2(f4, f5, ac[2]); UNPACK2(f6, f7, ac[3]);
        UNPACK2(g0, g1, ac[4]); UNPACK2(g2, g3, ac[5]);
        UNPACK2(g4, g5, ac[6]); UNPACK2(g6, g7, ac[7]);
        float gsum = pre_j + (((f0 + f1) + (f2 + f3)) + ((f4 + f5) + (f6 + f7)))
                           + (((g0 + g1) + (g2 + g3)) + ((g4 + g5) + (g6 + g7)));
        (void)r0; (void)r1; (void)r2; (void)r3;

        // activation: s = sigmoid(mul*g); tanh(g) = 2*sigmoid(2g)-1
        float sg = __fdividef(1.0f, 1.0f + __expf(-gate_mul * gsum));
        float a  = is_g ? (2.0f * sg - 1.0f) : sg;

        // publish act to BOTH CTAs via async stores (HW tx tracking)
        st_async_f32(dst_own[m],  a, mb_own[m]);
        st_async_f32(dst_peer[m], a, mb_peer[m]);

        // single wait covers local + remote acts
        mbar_wait(m ? mb1_l : mb0_l, par);
        if (tid == 0)  // re-arm this barrier for step s+2 (ordered by the
            mbar_expect_tx(m ? mb1_l : mb0_l, 2048);  // __syncthreads below)

        if (tid < 128) {
            const float* A = &act_all[m][0];
            float iv = A[tid];
            float fv = A[128 + tid];
            float gv = A[256 + tid];
            float ov = A[384 + tid];
            float dec = __expf(-fmaxf(tv * wt + bt, 0.0f));
            creg = fv * creg * dec + iv * gv;
            float hv = ov * fast_tanh(creg);
            hlast = hv;
            hbuf[cur ^ 1][tid] = hv;
            if (rank == 0)
                out[(size_t)t * (BB * HH) + (size_t)batch * HH + tid] = hv;
        }
        __syncthreads();   // h published; also orders re-arm before s+1 sends
    }

    // final state: h then c after the outputs block (rank0 only)
    if (rank == 0 && tid < 128) {
        size_t base = (size_t)SS * BB * HH;
        out[base + (size_t)batch * HH + tid] = hlast;
        out[base + (size_t)BB * HH + (size_t)batch * HH + tid] = creg;
    }

    cluster_sync_hw();   // no early exit while peer ops in flight
}

// ---------------------------------------------------------------------------
// Launch
// ---------------------------------------------------------------------------
extern "C" void kernel_launch(void* const* d_in, const int* in_sizes, int n_in,
                              void* d_out, int out_size)
{
    const float* X    = (const float*)d_in[0];  // input  (S,B,D)
    const float* Tm   = (const float*)d_in[1];  // time   (S,B,1)
    const float* Wih  = (const float*)d_in[2];  // (4H, D)
    const float* Whh  = (const float*)d_in[3];  // (4H, H)
    const float* bias = (const float*)d_in[4];  // (4H,)
    const float* wt   = (const float*)d_in[5];  // (H,)
    const float* bt   = (const float*)d_in[6];  // (H,)
    float* out = (float*)d_out;

    const int smemP = 2 * 128 * PSTRIDE * (int)sizeof(float);  // 135168 B
    cudaFuncSetAttribute(pre_gemm_kernel,
                         cudaFuncAttributeMaxDynamicSharedMemorySize, smemP);

    dim3 gridP((SS * BB) / 128, GG / 128);
    pre_gemm_kernel<<<gridP, 256, smemP>>>(X, Wih, bias);

    // 64 clusters of 2 CTAs (grid 128), 256 threads each
    lstm_rev_cluster_kernel<<<BB * 2, 256>>>(Tm, Whh, wt, bt, out);
}